// round 16
// baseline (speedup 1.0000x reference)
#include <cuda_runtime.h>
#include <cstdint>

// Problem constants (fixed by the dataset)
#define B_   16
#define S_   2048
#define D_   1024
#define P_   8192
#define R_   16

#define LCH  32               // rows per chunk == MAX_SPAN (load-bearing!)
#define NCH  (S_ / LCH)       // 64 chunks
#define OUTW (2 * D_ + R_)    // 2064 floats per output row

#define PAIRS_PER_BLK 2

// arr[b][s][d]: inclusive prefix of tok within the chunk containing s (flagged rows only)
__device__ float g_arr[(size_t)B_ * S_ * D_];            // ~134 MB address space, ~85 MB touched
__device__ float g_part[(size_t)B_ * NCH * D_];          // chunk totals (4 MB, L2-resident)
__device__ int   g_flag[(B_ * S_) / 4];                  // packed byte flags; zero at module load

// ---------------------------------------------------------------------------
// L2 eviction-priority via createpolicy + cache_hint (the ptxas-legal form for
// 16-byte accesses on sm_103): arr/part pinned evict_last; tok/out stream (.cs).
__device__ __forceinline__ uint64_t pol_evict_last() {
    uint64_t pol;
    asm("createpolicy.fractional.L2::evict_last.b64 %0, 1.0;" : "=l"(pol));
    return pol;
}
__device__ __forceinline__ void stg_el(float4* p, float4 v, uint64_t pol) {
    asm volatile("st.global.L2::cache_hint.v4.f32 [%0], {%1,%2,%3,%4}, %5;"
                 :: "l"(p), "f"(v.x), "f"(v.y), "f"(v.z), "f"(v.w), "l"(pol) : "memory");
}
__device__ __forceinline__ float4 ldg_el(const float4* p, uint64_t pol) {
    float4 v;
    asm volatile("ld.global.L2::cache_hint.v4.f32 {%0,%1,%2,%3}, [%4], %5;"
                 : "=f"(v.x), "=f"(v.y), "=f"(v.z), "=f"(v.w) : "l"(p), "l"(pol));
    return v;
}

// ---------------------------------------------------------------------------
// Fused mark + rel-emit, one thread per PAIR (max MLP: 6 independent loads up
// front, one dependent rel_table row, then 4 flag bytes + 4 rel stores).
// Marking is IDEMPOTENT (only sets bytes to 1 from identical inputs each call;
// __device__ globals are zero-initialized at module load -> no zeroing pass).
__global__ void k_mark_rel(const int* __restrict__ batch_idx,
                           const int* __restrict__ e1s, const int* __restrict__ e1e,
                           const int* __restrict__ e2s, const int* __restrict__ e2e,
                           const int* __restrict__ rel_idx,
                           const float* __restrict__ rel_table,
                           float* __restrict__ out) {
    int p = blockIdx.x * blockDim.x + threadIdx.x;      // [0, P)
    if (p >= P_) return;

    // 6 independent loads issued back-to-back
    int b  = __ldg(batch_idx + p);
    int ri = __ldg(rel_idx + p);
    int a0 = __ldg(e1s + p);
    int a1 = __ldg(e1e + p);
    int a2 = __ldg(e2s + p);
    int a3 = __ldg(e2e + p);

    // dependent rel row (64 B, L2-hot table) -> streamed out
    const float4* rrow = (const float4*)(rel_table + (size_t)ri * R_);
    float4 r0 = __ldg(rrow + 0), r1 = __ldg(rrow + 1);
    float4 r2 = __ldg(rrow + 2), r3 = __ldg(rrow + 3);
    float4* od = (float4*)(out + (size_t)p * OUTW + 2 * D_);
    __stcs(od + 0, r0); __stcs(od + 1, r1);
    __stcs(od + 2, r2); __stcs(od + 3, r3);

    unsigned char* fl = (unsigned char*)g_flag + (size_t)b * S_;
    if (a0 > 0) fl[a0 - 1] = 1;
    if (a1 > 0) fl[a1 - 1] = 1;
    if (a2 > 0) fl[a2 - 1] = 1;
    if (a3 > 0) fl[a3 - 1] = 1;
}

// ---------------------------------------------------------------------------
// Single full-width tok pass (the measured 6.2 TB/s shape): per (b, chunk, d4)
// running prefix; write only flagged rows; emit chunk total unconditionally.
// tok read ONCE -> streaming (.cs); arr/part written evict_last to pin in L2.
__global__ void k_local_prefix(const float* __restrict__ tok) {
    __shared__ unsigned char sflag[LCH];
    int idx = blockIdx.x * blockDim.x + threadIdx.x;
    int d4   = idx & (D_ / 4 - 1);
    int rest = idx >> 8;                                  // D/4 = 256
    int ch   = rest & (NCH - 1);
    int b    = rest >> 6;                                 // NCH = 64

    if (threadIdx.x < LCH)
        sflag[threadIdx.x] = ((const unsigned char*)g_flag)[b * S_ + ch * LCH + threadIdx.x];
    __syncthreads();

    uint64_t pol = pol_evict_last();

    const float4* t  = (const float4*)(tok   + ((size_t)b * S_ + (size_t)ch * LCH) * D_) + d4;
    float4*       ar = (float4*)      (g_arr + ((size_t)b * S_ + (size_t)ch * LCH) * D_) + d4;

    float4 run = make_float4(0.f, 0.f, 0.f, 0.f);
#pragma unroll
    for (int i = 0; i < LCH; ++i) {
        float4 v = __ldcs(t + (size_t)i * (D_ / 4));     // streaming read
        run.x += v.x; run.y += v.y; run.z += v.z; run.w += v.w;
        if (sflag[i]) stg_el(ar + (size_t)i * (D_ / 4), run, pol);  // pin in L2
    }
    stg_el((float4*)(g_part + ((size_t)b * NCH + ch) * D_) + d4, run, pol);
}

// ---------------------------------------------------------------------------
// Span numerator: span <= LCH => endpoints in same or adjacent chunks:
//   s == 0           : cs[e] = arr[e-1]
//   same chunk       : cs[e]-cs[s] = arr[e-1] - arr[s-1]
//   adjacent chunks  : cs[e]-cs[s] = arr[e-1] - arr[s-1] + part[chunk(s-1)]
__device__ __forceinline__ float4 span_num(const float4* arr_b, const float4* part_b,
                                           int s, int f, int t, uint64_t pol) {
    float4 r = ldg_el(arr_b + (size_t)(f - 1) * (D_ / 4) + t, pol);
    if (s > 0) {
        float4 lo = ldg_el(arr_b + (size_t)(s - 1) * (D_ / 4) + t, pol);
        r.x -= lo.x; r.y -= lo.y; r.z -= lo.z; r.w -= lo.w;
        int cbs = (s - 1) >> 5;                 // LCH = 32
        int cbf = (f - 1) >> 5;
        if (cbf != cbs) {
            float4 br = ldg_el(part_b + (size_t)cbs * (D_ / 4) + t, pol);
            r.x += br.x; r.y += br.y; r.z += br.z; r.w += br.w;
        }
    }
    return r;
}

// Best-measured pairs shape: 512 threads = 2 pairs per block, 256 lanes each;
// out written with streaming stores so pinned arr keeps L2 priority. Rel
// columns are already written by k_mark_rel.
__global__ void k_pairs(const int* __restrict__ batch_idx,
                        const int* __restrict__ e1s, const int* __restrict__ e1e,
                        const int* __restrict__ e2s, const int* __restrict__ e2e,
                        float* __restrict__ out) {
    int p = blockIdx.x * PAIRS_PER_BLK + (threadIdx.x >> 8);
    int t = threadIdx.x & 255;          // float4 lane

    int b  = __ldg(batch_idx + p);
    int s1 = __ldg(e1s + p), f1 = __ldg(e1e + p);
    int s2 = __ldg(e2s + p), f2 = __ldg(e2e + p);

    uint64_t pol = pol_evict_last();

    const float4* arr_b  = (const float4*)(g_arr  + (size_t)b * S_ * D_);
    const float4* part_b = (const float4*)(g_part + (size_t)b * NCH * D_);
    float4* orow = (float4*)(out + (size_t)p * OUTW);

    float inv1 = 1.0f / (float)(f1 - s1);
    float inv2 = 1.0f / (float)(f2 - s2);

    float4 n1 = span_num(arr_b, part_b, s1, f1, t, pol);
    __stcs(orow + t, make_float4(n1.x * inv1, n1.y * inv1, n1.z * inv1, n1.w * inv1));

    float4 n2 = span_num(arr_b, part_b, s2, f2, t, pol);
    __stcs(orow + D_ / 4 + t,
           make_float4(n2.x * inv2, n2.y * inv2, n2.z * inv2, n2.w * inv2));
}

// ---------------------------------------------------------------------------
extern "C" void kernel_launch(void* const* d_in, const int* in_sizes, int n_in,
                              void* d_out, int out_size) {
    const float* tok       = (const float*)d_in[0];
    const int*   batch_idx = (const int*)d_in[1];
    const int*   e1s       = (const int*)d_in[2];
    const int*   e1e       = (const int*)d_in[3];
    const int*   e2s       = (const int*)d_in[4];
    const int*   e2e       = (const int*)d_in[5];
    const int*   rel_idx   = (const int*)d_in[6];
    const float* rel_table = (const float*)d_in[7];
    float* out = (float*)d_out;

    (void)in_sizes; (void)n_in; (void)out_size;

    k_mark_rel<<<(P_ + 255) / 256, 256>>>(batch_idx, e1s, e1e, e2s, e2e,
                                          rel_idx, rel_table, out);
    k_local_prefix<<<B_ * NCH * (D_ / 4) / 256, 256>>>(tok);
    k_pairs<<<P_ / PAIRS_PER_BLK, 256 * PAIRS_PER_BLK>>>(batch_idx, e1s, e1e, e2s, e2e, out);
}

// round 17
// speedup vs baseline: 1.0047x; 1.0047x over previous
#include <cuda_runtime.h>
#include <cstdint>

// Problem constants (fixed by the dataset)
#define B_   16
#define S_   2048
#define D_   1024
#define P_   8192
#define R_   16

#define LCH  32               // rows per chunk == MAX_SPAN (load-bearing!)
#define NCH  (S_ / LCH)       // 64 chunks
#define OUTW (2 * D_ + R_)    // 2064 floats per output row

#define PAIRS_PER_BLK 2

// arr[b][s][d]: inclusive prefix of tok within the chunk containing s (flagged rows only)
__device__ float g_arr[(size_t)B_ * S_ * D_];            // ~134 MB address space, ~85 MB touched
__device__ float g_part[(size_t)B_ * NCH * D_];          // chunk totals (4 MB, L2-resident)
__device__ int   g_flag[(B_ * S_) / 4];                  // packed byte flags; zero at module load

// ---------------------------------------------------------------------------
// Fused mark + rel-emit, one thread per PAIR. Grid = 512 blocks x 16 threads:
// grid >= 148 avoids the B300 small-grid issue throttle and spreads the
// dependent-load chains across all SMs' L1tex queues.
// Marking is IDEMPOTENT (only sets bytes to 1 from identical inputs each call;
// __device__ globals are zero-initialized at module load -> no zeroing pass).
__global__ void k_mark_rel(const int* __restrict__ batch_idx,
                           const int* __restrict__ e1s, const int* __restrict__ e1e,
                           const int* __restrict__ e2s, const int* __restrict__ e2e,
                           const int* __restrict__ rel_idx,
                           const float* __restrict__ rel_table,
                           float* __restrict__ out) {
    int p = blockIdx.x * blockDim.x + threadIdx.x;      // [0, P)
    if (p >= P_) return;

    // 6 independent loads issued back-to-back
    int b  = __ldg(batch_idx + p);
    int ri = __ldg(rel_idx + p);
    int a0 = __ldg(e1s + p);
    int a1 = __ldg(e1e + p);
    int a2 = __ldg(e2s + p);
    int a3 = __ldg(e2e + p);

    // dependent rel row (64 B, L2-hot table) -> streamed out
    const float4* rrow = (const float4*)(rel_table + (size_t)ri * R_);
    float4 r0 = __ldg(rrow + 0), r1 = __ldg(rrow + 1);
    float4 r2 = __ldg(rrow + 2), r3 = __ldg(rrow + 3);
    float4* od = (float4*)(out + (size_t)p * OUTW + 2 * D_);
    __stcs(od + 0, r0); __stcs(od + 1, r1);
    __stcs(od + 2, r2); __stcs(od + 3, r3);

    unsigned char* fl = (unsigned char*)g_flag + (size_t)b * S_;
    if (a0 > 0) fl[a0 - 1] = 1;
    if (a1 > 0) fl[a1 - 1] = 1;
    if (a2 > 0) fl[a2 - 1] = 1;
    if (a3 > 0) fl[a3 - 1] = 1;
}

// ---------------------------------------------------------------------------
// Single full-width tok pass (the measured 6.2+ TB/s shape): per (b, chunk, d4)
// running prefix; write only flagged rows; emit chunk total unconditionally.
// tok read ONCE -> streaming (.cs) so arr/part keep L2 priority by default.
__global__ void k_local_prefix(const float* __restrict__ tok) {
    __shared__ unsigned char sflag[LCH];
    int idx = blockIdx.x * blockDim.x + threadIdx.x;
    int d4   = idx & (D_ / 4 - 1);
    int rest = idx >> 8;                                  // D/4 = 256
    int ch   = rest & (NCH - 1);
    int b    = rest >> 6;                                 // NCH = 64

    if (threadIdx.x < LCH)
        sflag[threadIdx.x] = ((const unsigned char*)g_flag)[b * S_ + ch * LCH + threadIdx.x];
    __syncthreads();

    const float4* t  = (const float4*)(tok   + ((size_t)b * S_ + (size_t)ch * LCH) * D_) + d4;
    float4*       ar = (float4*)      (g_arr + ((size_t)b * S_ + (size_t)ch * LCH) * D_) + d4;

    float4 run = make_float4(0.f, 0.f, 0.f, 0.f);
#pragma unroll
    for (int i = 0; i < LCH; ++i) {
        float4 v = __ldcs(t + (size_t)i * (D_ / 4));     // streaming read
        run.x += v.x; run.y += v.y; run.z += v.z; run.w += v.w;
        if (sflag[i]) ar[(size_t)i * (D_ / 4)] = run;    // keep in L2
    }
    ((float4*)(g_part + ((size_t)b * NCH + ch) * D_))[d4] = run;
}

// ---------------------------------------------------------------------------
// Span numerator: span <= LCH => endpoints in same or adjacent chunks:
//   s == 0           : cs[e] = arr[e-1]
//   same chunk       : cs[e]-cs[s] = arr[e-1] - arr[s-1]
//   adjacent chunks  : cs[e]-cs[s] = arr[e-1] - arr[s-1] + part[chunk(s-1)]
__device__ __forceinline__ float4 span_num(const float4* arr_b, const float4* part_b,
                                           int s, int f, int t) {
    float4 r = arr_b[(size_t)(f - 1) * (D_ / 4) + t];
    if (s > 0) {
        float4 lo = arr_b[(size_t)(s - 1) * (D_ / 4) + t];
        r.x -= lo.x; r.y -= lo.y; r.z -= lo.z; r.w -= lo.w;
        int cbs = (s - 1) >> 5;                 // LCH = 32
        int cbf = (f - 1) >> 5;
        if (cbf != cbs) {
            float4 br = part_b[(size_t)cbs * (D_ / 4) + t];
            r.x += br.x; r.y += br.y; r.z += br.z; r.w += br.w;
        }
    }
    return r;
}

// Best-measured pairs shape: 512 threads = 2 pairs per block, 256 lanes each;
// out written with streaming stores so arr keeps L2 priority. Rel columns are
// already written by k_mark_rel.
__global__ void k_pairs(const int* __restrict__ batch_idx,
                        const int* __restrict__ e1s, const int* __restrict__ e1e,
                        const int* __restrict__ e2s, const int* __restrict__ e2e,
                        float* __restrict__ out) {
    int p = blockIdx.x * PAIRS_PER_BLK + (threadIdx.x >> 8);
    int t = threadIdx.x & 255;          // float4 lane

    int b  = __ldg(batch_idx + p);
    int s1 = __ldg(e1s + p), f1 = __ldg(e1e + p);
    int s2 = __ldg(e2s + p), f2 = __ldg(e2e + p);

    const float4* arr_b  = (const float4*)(g_arr  + (size_t)b * S_ * D_);
    const float4* part_b = (const float4*)(g_part + (size_t)b * NCH * D_);
    float4* orow = (float4*)(out + (size_t)p * OUTW);

    float inv1 = 1.0f / (float)(f1 - s1);
    float inv2 = 1.0f / (float)(f2 - s2);

    float4 n1 = span_num(arr_b, part_b, s1, f1, t);
    __stcs(orow + t, make_float4(n1.x * inv1, n1.y * inv1, n1.z * inv1, n1.w * inv1));

    float4 n2 = span_num(arr_b, part_b, s2, f2, t);
    __stcs(orow + D_ / 4 + t,
           make_float4(n2.x * inv2, n2.y * inv2, n2.z * inv2, n2.w * inv2));
}

// ---------------------------------------------------------------------------
extern "C" void kernel_launch(void* const* d_in, const int* in_sizes, int n_in,
                              void* d_out, int out_size) {
    const float* tok       = (const float*)d_in[0];
    const int*   batch_idx = (const int*)d_in[1];
    const int*   e1s       = (const int*)d_in[2];
    const int*   e1e       = (const int*)d_in[3];
    const int*   e2s       = (const int*)d_in[4];
    const int*   e2e       = (const int*)d_in[5];
    const int*   rel_idx   = (const int*)d_in[6];
    const float* rel_table = (const float*)d_in[7];
    float* out = (float*)d_out;

    (void)in_sizes; (void)n_in; (void)out_size;

    k_mark_rel<<<P_ / 16, 16>>>(batch_idx, e1s, e1e, e2s, e2e,
                                rel_idx, rel_table, out);
    k_local_prefix<<<B_ * NCH * (D_ / 4) / 256, 256>>>(tok);
    k_pairs<<<P_ / PAIRS_PER_BLK, 256 * PAIRS_PER_BLK>>>(batch_idx, e1s, e1e, e2s, e2e, out);
}